// round 1
// baseline (speedup 1.0000x reference)
#include <cuda_runtime.h>
#include <cstdint>

// VectorQuantizer: z[16,256,32,32] fp32, codebook[16384,256] fp32
// out: z_q [16,32,32,256] flattened (4,194,304 floats) then idx (16384) as float.

#define NROWS 16384
#define KCODES 16384
#define NZQ (16384*256)

typedef unsigned long long ull;

// ---- scratch (device globals; no allocation allowed) ----
__device__ float4 g_zt4[NROWS * 64];   // z transposed to [N][256], 16 MB
__device__ float  g_zn2[NROWS];
__device__ float  g_ce[KCODES];
__device__ int    g_idx[NROWS];

// =====================================================================
// transpose z [B=16, C=256, HW=1024] -> zt [n = b*1024+hw][c]
// =====================================================================
__global__ void k_transpose(const float* __restrict__ z) {
    __shared__ float t[32][33];
    int b = blockIdx.z, c0 = blockIdx.y * 32, hw0 = blockIdx.x * 32;
    float* zt = (float*)g_zt4;
#pragma unroll
    for (int r = 0; r < 4; r++) {
        int c = c0 + threadIdx.y + 8 * r;
        t[threadIdx.y + 8 * r][threadIdx.x] =
            z[((size_t)(b * 256 + c)) * 1024 + hw0 + threadIdx.x];
    }
    __syncthreads();
#pragma unroll
    for (int r = 0; r < 4; r++) {
        int hw = hw0 + threadIdx.y + 8 * r;
        zt[((size_t)(b * 1024 + hw)) * 256 + c0 + threadIdx.x] =
            t[threadIdx.x][threadIdx.y + 8 * r];
    }
}

// =====================================================================
// row squared norms. Replicates XLA-CPU semantics: square is a separate
// rounded multiply, then a STRICTLY SEQUENTIAL left-to-right fp32 add
// chain (no fma, no reassociation). 32 rows per block; rows staged in
// smem (padded) so the serial phase reads conflict-free.
// =====================================================================
__global__ void k_rownorm(const float* __restrict__ src, float* __restrict__ dst) {
    __shared__ float s[32 * 257];
    int base = blockIdx.x * 32;
    for (int off = threadIdx.x; off < 32 * 256; off += 256) {
        int r = off >> 8, d = off & 255;
        s[r * 257 + d] = src[(size_t)base * 256 + off];
    }
    __syncthreads();
    if (threadIdx.x < 32) {
        const float* row = &s[threadIdx.x * 257];
        float a = 0.f;
        for (int d = 0; d < 256; ++d) {
            float v = row[d];
            a = __fadd_rn(a, __fmul_rn(v, v));   // mul rounds, then add: matches XLA reduce
        }
        dst[base + threadIdx.x] = a;
    }
}

// =====================================================================
// fused distance-GEMM + argmin
// =====================================================================
__device__ __forceinline__ ull pk2(float lo, float hi) {
    ull r; asm("mov.b64 %0, {%1, %2};" : "=l"(r) : "f"(lo), "f"(hi)); return r;
}
__device__ __forceinline__ void unpk2(ull v, float& lo, float& hi) {
    asm("mov.b64 {%0, %1}, %2;" : "=f"(lo), "=f"(hi) : "l"(v));
}
__device__ __forceinline__ void ffma2(ull& d, ull a, ull b) {
    asm("fma.rn.f32x2 %0, %1, %2, %0;" : "+l"(d) : "l"(a), "l"(b));
}
__device__ __forceinline__ void cpa16(void* dst, const void* src) {
    unsigned s = (unsigned)__cvta_generic_to_shared(dst);
    asm volatile("cp.async.cg.shared.global [%0], [%1], 16;" :: "r"(s), "l"(src));
}

// Block: 256 threads, tile 128 rows x 128 codes, K chunks of 32 floats,
// double-buffered cp.async. Thread (tx=tid%16, ty=tid/16) owns rows
// {ty+16i} and codes {tx+16j} (lane-adjacent codes -> conflict-free LDS.128).
// Smem row pitch = 9 float4 (36 floats) for bank spread.
__global__ __launch_bounds__(256, 1) void k_argmin(const float4* __restrict__ cb4) {
    extern __shared__ float4 smem4[];
    float4* sZ = smem4;              // [2][128*9]
    float4* sC = smem4 + 2 * 1152;   // [2][128*9]
    const int tid = threadIdx.x;
    const int tx = tid & 15, ty = tid >> 4;
    const int rowbase = blockIdx.x * 128;
    const int ld_d4 = tid & 7, ld_r = tid >> 3;

    float minv[8]; int mini[8]; float zn2r[8];
#pragma unroll
    for (int i = 0; i < 8; i++) {
        minv[i] = __int_as_float(0x7f800000);
        mini[i] = 0;
        zn2r[i] = g_zn2[rowbase + ty + 16 * i];
    }

    const float4* zt4 = g_zt4;
    // prologue: issue chunk (kt=0, ch=0) into buffer 0
    {
#pragma unroll
        for (int p = 0; p < 4; p++) {
            int r = ld_r + 32 * p;
            cpa16(&sZ[r * 9 + ld_d4], &zt4[(size_t)(rowbase + r) * 64 + ld_d4]);
            cpa16(&sC[r * 9 + ld_d4], &cb4[(size_t)r * 64 + ld_d4]);
        }
        asm volatile("cp.async.commit_group;" ::: "memory");
    }

    int buf = 0;
    for (int kt = 0; kt < 128; ++kt) {
        ull acc[8][4];
#pragma unroll
        for (int i = 0; i < 8; i++)
#pragma unroll
            for (int jp = 0; jp < 4; jp++) acc[i][jp] = 0ull;

        for (int ch = 0; ch < 8; ++ch) {
            asm volatile("cp.async.wait_group 0;" ::: "memory");
            __syncthreads();
            // prefetch next chunk into the other buffer
            int nkt = kt, nch = ch + 1;
            if (nch == 8) { nch = 0; nkt = kt + 1; }
            if (nkt < 128) {
                float4* dZ = sZ + (buf ^ 1) * 1152;
                float4* dC = sC + (buf ^ 1) * 1152;
#pragma unroll
                for (int p = 0; p < 4; p++) {
                    int r = ld_r + 32 * p;
                    cpa16(&dZ[r * 9 + ld_d4],
                          &zt4[(size_t)(rowbase + r) * 64 + nch * 8 + ld_d4]);
                    cpa16(&dC[r * 9 + ld_d4],
                          &cb4[(size_t)(nkt * 128 + r) * 64 + nch * 8 + ld_d4]);
                }
                asm volatile("cp.async.commit_group;" ::: "memory");
            }
            // compute current buffer: 32 d-values
            const float4* Zb = sZ + buf * 1152;
            const float4* Cb = sC + buf * 1152;
#pragma unroll
            for (int d4 = 0; d4 < 8; ++d4) {
                ull cpx[4], cpy[4], cpz[4], cpw[4];
#pragma unroll
                for (int jp = 0; jp < 4; jp++) {
                    float4 c0 = Cb[(tx + 32 * jp) * 9 + d4];
                    float4 c1 = Cb[(tx + 32 * jp + 16) * 9 + d4];
                    cpx[jp] = pk2(c0.x, c1.x); cpy[jp] = pk2(c0.y, c1.y);
                    cpz[jp] = pk2(c0.z, c1.z); cpw[jp] = pk2(c0.w, c1.w);
                }
#pragma unroll
                for (int i = 0; i < 8; i++) {
                    float4 zv = Zb[(ty + 16 * i) * 9 + d4];
                    ull zx = pk2(zv.x, zv.x), zy = pk2(zv.y, zv.y);
                    ull zz = pk2(zv.z, zv.z), zw = pk2(zv.w, zv.w);
#pragma unroll
                    for (int jp = 0; jp < 4; jp++) {
                        ffma2(acc[i][jp], zx, cpx[jp]);
                        ffma2(acc[i][jp], zy, cpy[jp]);
                        ffma2(acc[i][jp], zz, cpz[jp]);
                        ffma2(acc[i][jp], zw, cpw[jp]);
                    }
                }
            }
            buf ^= 1;
        }
        // epilogue: scores for this code tile; replicate reference rounding:
        // d = fl( fl(zn2 + ce) - fl(2*g) )   (2*g is exact; fused sub ok)
        int ktb = kt * 128;
#pragma unroll
        for (int i = 0; i < 8; i++) {
            float zn = zn2r[i];
#pragma unroll
            for (int jp = 0; jp < 4; jp++) {
                float g0, g1; unpk2(acc[i][jp], g0, g1);
                int c0 = ktb + tx + 32 * jp;
                int c1 = c0 + 16;
                float t0 = __fadd_rn(zn, __ldg(&g_ce[c0]));
                float t1 = __fadd_rn(zn, __ldg(&g_ce[c1]));
                float s0 = __fmaf_rn(-2.0f, g0, t0);
                float s1 = __fmaf_rn(-2.0f, g1, t1);
                // strict <: codes visited in ascending order per thread ->
                // earliest (lowest) index wins on exact ties, like jnp.argmin
                if (s0 < minv[i]) { minv[i] = s0; mini[i] = c0; }
                if (s1 < minv[i]) { minv[i] = s1; mini[i] = c1; }
            }
        }
    }

    // cross-lane (tx) reduction, tie-break to lowest index
    __syncthreads();
    float* rv = (float*)smem4;
    int*   ri = (int*)(((char*)smem4) + 128 * 17 * 4);
#pragma unroll
    for (int i = 0; i < 8; i++) {
        int rl = ty + 16 * i;
        rv[rl * 17 + tx] = minv[i];
        ri[rl * 17 + tx] = mini[i];
    }
    __syncthreads();
    if (tid < 128) {
        float bv = rv[tid * 17]; int bi = ri[tid * 17];
#pragma unroll
        for (int t = 1; t < 16; t++) {
            float v = rv[tid * 17 + t]; int id = ri[tid * 17 + t];
            if (v < bv || (v == bv && id < bi)) { bv = v; bi = id; }
        }
        g_idx[rowbase + tid] = bi;
    }
}

// =====================================================================
// gather z_q = codebook[idx] and append idx (as float) if room
// =====================================================================
__global__ void k_gather(const float4* __restrict__ cb4, float* __restrict__ out,
                         int write_idx) {
    int t = blockIdx.x * 256 + threadIdx.x;
    int n = t >> 6, c4 = t & 63;
    int id = g_idx[n];
    ((float4*)out)[(size_t)n * 64 + c4] = cb4[(size_t)id * 64 + c4];
    if (write_idx && c4 == 0) out[NZQ + n] = (float)id;
}

// =====================================================================
extern "C" void kernel_launch(void* const* d_in, const int* in_sizes, int n_in,
                              void* d_out, int out_size) {
    const float* z  = (const float*)d_in[0];
    const float* cb = (const float*)d_in[1];

    void *ztp, *zn2p, *cep;
    cudaGetSymbolAddress(&ztp, g_zt4);
    cudaGetSymbolAddress(&zn2p, g_zn2);
    cudaGetSymbolAddress(&cep, g_ce);

    k_transpose<<<dim3(32, 8, 16), dim3(32, 8)>>>(z);
    k_rownorm<<<512, 256>>>((const float*)ztp, (float*)zn2p);
    k_rownorm<<<512, 256>>>(cb, (float*)cep);

    const int smem_bytes = 4608 * 16;  // 2 bufs x (Z+C) x 1152 float4 = 73728 B
    cudaFuncSetAttribute(k_argmin, cudaFuncAttributeMaxDynamicSharedMemorySize,
                         smem_bytes);
    k_argmin<<<128, 256, smem_bytes>>>((const float4*)cb);

    int write_idx = (out_size >= NZQ + NROWS) ? 1 : 0;
    k_gather<<<(NROWS * 64) / 256, 256>>>((const float4*)cb, (float*)d_out, write_idx);
}

// round 4
// speedup vs baseline: 1.4352x; 1.4352x over previous
#include <cuda_runtime.h>
#include <cstdint>

// VectorQuantizer: z[16,256,32,32] fp32, codebook[16384,256] fp32
// out: z_q [16,32,32,256] flattened (4,194,304 floats) then idx (16384) as float.

#define NROWS 16384
#define KCODES 16384
#define NZQ (16384*256)

typedef unsigned long long ull;

// ---- scratch (device globals; no allocation allowed) ----
__device__ float4 g_zt4[NROWS * 64];   // z transposed to [N][256], 16 MB
__device__ float  g_zn2[NROWS];
__device__ float  g_ce[KCODES];
__device__ int    g_idx[NROWS];

// =====================================================================
// transpose z [B=16, C=256, HW=1024] -> zt [n = b*1024+hw][c]
// =====================================================================
__global__ void k_transpose(const float* __restrict__ z) {
    __shared__ float t[32][33];
    int b = blockIdx.z, c0 = blockIdx.y * 32, hw0 = blockIdx.x * 32;
    float* zt = (float*)g_zt4;
#pragma unroll
    for (int r = 0; r < 4; r++) {
        int c = c0 + threadIdx.y + 8 * r;
        t[threadIdx.y + 8 * r][threadIdx.x] =
            z[((size_t)(b * 256 + c)) * 1024 + hw0 + threadIdx.x];
    }
    __syncthreads();
#pragma unroll
    for (int r = 0; r < 4; r++) {
        int hw = hw0 + threadIdx.y + 8 * r;
        zt[((size_t)(b * 1024 + hw)) * 256 + c0 + threadIdx.x] =
            t[threadIdx.x][threadIdx.y + 8 * r];
    }
}

// =====================================================================
// row squared norms: separate rounded multiply then strictly sequential
// left-to-right fp32 add chain (matches XLA reduce semantics).
// =====================================================================
__global__ void k_rownorm(const float* __restrict__ src, float* __restrict__ dst) {
    __shared__ float s[32 * 257];
    int base = blockIdx.x * 32;
    for (int off = threadIdx.x; off < 32 * 256; off += 256) {
        int r = off >> 8, d = off & 255;
        s[r * 257 + d] = src[(size_t)base * 256 + off];
    }
    __syncthreads();
    if (threadIdx.x < 32) {
        const float* row = &s[threadIdx.x * 257];
        float a = 0.f;
        for (int d = 0; d < 256; ++d) {
            float v = row[d];
            a = __fadd_rn(a, __fmul_rn(v, v));
        }
        dst[base + threadIdx.x] = a;
    }
}

// =====================================================================
// fused distance-GEMM + argmin
// =====================================================================
__device__ __forceinline__ void unpk2(ull v, float& lo, float& hi) {
    asm("mov.b64 {%0, %1}, %2;" : "=f"(lo), "=f"(hi) : "l"(v));
}
__device__ __forceinline__ void ffma2(ull& d, ull a, ull b) {
    asm("fma.rn.f32x2 %0, %1, %2, %0;" : "+l"(d) : "l"(a), "l"(b));
}
__device__ __forceinline__ void cpa16(void* dst, const void* src) {
    unsigned s = (unsigned)__cvta_generic_to_shared(dst);
    asm volatile("cp.async.cg.shared.global [%0], [%1], 16;" :: "r"(s), "l"(src));
}

// Block: 256 threads, tile 128 rows x 128 codes, K chunks of 32 floats,
// double-buffered cp.async. Thread (tx=tid%16, ty=tid/16) owns rows
// {ty+16i, i<8} and codes {tx+16j, j<8}.
// f32x2 packing is over the d-dimension: one LDS.128 yields two aligned
// (d,d+1) pairs for both operands -> ZERO packing MOVs. Each (row,code)
// keeps one f32x2 accumulator (even-d half, odd-d half), combined with a
// single fadd per score at code-tile end.
// Smem row pitch = 36 floats (144 B) for conflict-free 8-lane phases.
__global__ __launch_bounds__(256, 1) void k_argmin(const float4* __restrict__ cb4) {
    extern __shared__ float4 smem4[];
    char* sZ = (char*)smem4;                 // [2][128*144]
    char* sC = (char*)(smem4 + 2 * 1152);    // [2][128*144]
    const int tid = threadIdx.x;
    const int tx = tid & 15, ty = tid >> 4;
    const int rowbase = blockIdx.x * 128;
    const int ld_d4 = tid & 7, ld_r = tid >> 3;

    float minv[8]; int mini[8]; float zn2r[8];
#pragma unroll
    for (int i = 0; i < 8; i++) {
        minv[i] = __int_as_float(0x7f800000);
        mini[i] = 0;
        zn2r[i] = g_zn2[rowbase + ty + 16 * i];
    }

    const float4* zt4 = g_zt4;
    // prologue: issue chunk (kt=0, ch=0) into buffer 0
    {
#pragma unroll
        for (int p = 0; p < 4; p++) {
            int r = ld_r + 32 * p;
            cpa16(sZ + r * 144 + ld_d4 * 16, &zt4[(size_t)(rowbase + r) * 64 + ld_d4]);
            cpa16(sC + r * 144 + ld_d4 * 16, &cb4[(size_t)r * 64 + ld_d4]);
        }
        asm volatile("cp.async.commit_group;" ::: "memory");
    }

    int buf = 0;
    for (int kt = 0; kt < 128; ++kt) {
        const int ktb = kt * 128;
        // prefetch ce for this code tile (consumed only at tile end)
        float ce_r[8];
#pragma unroll
        for (int j = 0; j < 8; j++) ce_r[j] = __ldg(&g_ce[ktb + tx + 16 * j]);

        ull acc[8][8];
#pragma unroll
        for (int i = 0; i < 8; i++)
#pragma unroll
            for (int j = 0; j < 8; j++) acc[i][j] = 0ull;

        for (int ch = 0; ch < 8; ++ch) {
            asm volatile("cp.async.wait_group 0;" ::: "memory");
            __syncthreads();
            // prefetch next chunk into the other buffer
            int nkt = kt, nch = ch + 1;
            if (nch == 8) { nch = 0; nkt = kt + 1; }
            if (nkt < 128) {
                char* dZ = sZ + (buf ^ 1) * 18432;
                char* dC = sC + (buf ^ 1) * 18432;
#pragma unroll
                for (int p = 0; p < 4; p++) {
                    int r = ld_r + 32 * p;
                    cpa16(dZ + r * 144 + ld_d4 * 16,
                          &zt4[(size_t)(rowbase + r) * 64 + nch * 8 + ld_d4]);
                    cpa16(dC + r * 144 + ld_d4 * 16,
                          &cb4[(size_t)(nkt * 128 + r) * 64 + nch * 8 + ld_d4]);
                }
                asm volatile("cp.async.commit_group;" ::: "memory");
            }
            // compute current buffer: 32 d-values
            const char* Zb = sZ + buf * 18432;
            const char* Cb = sC + buf * 18432;
#pragma unroll
            for (int d4 = 0; d4 < 8; ++d4) {
                ulonglong2 c[8];
#pragma unroll
                for (int j = 0; j < 8; j++)
                    c[j] = *(const ulonglong2*)(Cb + (tx + 16 * j) * 144 + d4 * 16);
#pragma unroll
                for (int i = 0; i < 8; i++) {
                    ulonglong2 zv =
                        *(const ulonglong2*)(Zb + (ty + 16 * i) * 144 + d4 * 16);
#pragma unroll
                    for (int j = 0; j < 8; j++) {
                        ffma2(acc[i][j], zv.x, c[j].x);
                        ffma2(acc[i][j], zv.y, c[j].y);
                    }
                }
            }
            buf ^= 1;
        }
        // epilogue: scores; d = fl( fl(zn2 + ce) - fl(2*g) )
#pragma unroll
        for (int i = 0; i < 8; i++) {
            float zn = zn2r[i];
#pragma unroll
            for (int j = 0; j < 8; j++) {
                float lo, hi; unpk2(acc[i][j], lo, hi);
                float g = __fadd_rn(lo, hi);
                int cidx = ktb + tx + 16 * j;
                float t = __fadd_rn(zn, ce_r[j]);
                float s = __fmaf_rn(-2.0f, g, t);
                // strict <: codes visited ascending -> lowest index wins ties
                if (s < minv[i]) { minv[i] = s; mini[i] = cidx; }
            }
        }
    }

    // cross-lane (tx) reduction, tie-break to lowest index
    __syncthreads();
    float* rv = (float*)smem4;
    int*   ri = (int*)(((char*)smem4) + 128 * 17 * 4);
#pragma unroll
    for (int i = 0; i < 8; i++) {
        int rl = ty + 16 * i;
        rv[rl * 17 + tx] = minv[i];
        ri[rl * 17 + tx] = mini[i];
    }
    __syncthreads();
    if (tid < 128) {
        float bv = rv[tid * 17]; int bi = ri[tid * 17];
#pragma unroll
        for (int t = 1; t < 16; t++) {
            float v = rv[tid * 17 + t]; int id = ri[tid * 17 + t];
            if (v < bv || (v == bv && id < bi)) { bv = v; bi = id; }
        }
        g_idx[rowbase + tid] = bi;
    }
}

// =====================================================================
// gather z_q = codebook[idx] and append idx (as float) if room
// =====================================================================
__global__ void k_gather(const float4* __restrict__ cb4, float* __restrict__ out,
                         int write_idx) {
    int t = blockIdx.x * 256 + threadIdx.x;
    int n = t >> 6, c4 = t & 63;
    int id = g_idx[n];
    ((float4*)out)[(size_t)n * 64 + c4] = cb4[(size_t)id * 64 + c4];
    if (write_idx && c4 == 0) out[NZQ + n] = (float)id;
}

// =====================================================================
extern "C" void kernel_launch(void* const* d_in, const int* in_sizes, int n_in,
                              void* d_out, int out_size) {
    const float* z  = (const float*)d_in[0];
    const float* cb = (const float*)d_in[1];

    void *ztp, *zn2p, *cep;
    cudaGetSymbolAddress(&ztp, g_zt4);
    cudaGetSymbolAddress(&zn2p, g_zn2);
    cudaGetSymbolAddress(&cep, g_ce);

    k_transpose<<<dim3(32, 8, 16), dim3(32, 8)>>>(z);
    k_rownorm<<<512, 256>>>((const float*)ztp, (float*)zn2p);
    k_rownorm<<<512, 256>>>(cb, (float*)cep);

    const int smem_bytes = 4608 * 16;  // 2 bufs x (Z+C) x 18432 B = 73728 B
    cudaFuncSetAttribute(k_argmin, cudaFuncAttributeMaxDynamicSharedMemorySize,
                         smem_bytes);
    k_argmin<<<128, 256, smem_bytes>>>((const float4*)cb);

    int write_idx = (out_size >= NZQ + NROWS) ? 1 : 0;
    k_gather<<<(NROWS * 64) / 256, 256>>>((const float4*)cb, (float*)d_out, write_idx);
}

// round 5
// speedup vs baseline: 1.4694x; 1.0239x over previous
#include <cuda_runtime.h>
#include <cstdint>

// VectorQuantizer: z[16,256,32,32] fp32, codebook[16384,256] fp32
// out: z_q [16,32,32,256] flattened (4,194,304 floats) then idx (16384) as float.

#define NROWS 16384
#define KCODES 16384
#define NZQ (16384*256)

typedef unsigned long long ull;

// ---- scratch (device globals; no allocation allowed) ----
__device__ float4 g_zt4[NROWS * 64];   // z transposed to [N][256], 16 MB
__device__ float  g_zn2[NROWS];
__device__ float  g_ce[KCODES];
__device__ int    g_idx[NROWS];

// =====================================================================
// transpose z [B=16, C=256, HW=1024] -> zt [n = b*1024+hw][c]
// =====================================================================
__global__ void k_transpose(const float* __restrict__ z) {
    __shared__ float t[32][33];
    int b = blockIdx.z, c0 = blockIdx.y * 32, hw0 = blockIdx.x * 32;
    float* zt = (float*)g_zt4;
#pragma unroll
    for (int r = 0; r < 4; r++) {
        int c = c0 + threadIdx.y + 8 * r;
        t[threadIdx.y + 8 * r][threadIdx.x] =
            z[((size_t)(b * 256 + c)) * 1024 + hw0 + threadIdx.x];
    }
    __syncthreads();
#pragma unroll
    for (int r = 0; r < 4; r++) {
        int hw = hw0 + threadIdx.y + 8 * r;
        zt[((size_t)(b * 1024 + hw)) * 256 + c0 + threadIdx.x] =
            t[threadIdx.x][threadIdx.y + 8 * r];
    }
}

// =====================================================================
// row squared norms: separate rounded multiply then strictly sequential
// left-to-right fp32 add chain (matches XLA reduce semantics).
// =====================================================================
__global__ void k_rownorm(const float* __restrict__ src, float* __restrict__ dst) {
    __shared__ float s[32 * 257];
    int base = blockIdx.x * 32;
    for (int off = threadIdx.x; off < 32 * 256; off += 256) {
        int r = off >> 8, d = off & 255;
        s[r * 257 + d] = src[(size_t)base * 256 + off];
    }
    __syncthreads();
    if (threadIdx.x < 32) {
        const float* row = &s[threadIdx.x * 257];
        float a = 0.f;
        for (int d = 0; d < 256; ++d) {
            float v = row[d];
            a = __fadd_rn(a, __fmul_rn(v, v));
        }
        dst[base + threadIdx.x] = a;
    }
}

// =====================================================================
// fused distance-GEMM + argmin
// =====================================================================
__device__ __forceinline__ void unpk2(ull v, float& lo, float& hi) {
    asm("mov.b64 {%0, %1}, %2;" : "=f"(lo), "=f"(hi) : "l"(v));
}
__device__ __forceinline__ void ffma2(ull& d, ull a, ull b) {
    asm("fma.rn.f32x2 %0, %1, %2, %0;" : "+l"(d) : "l"(a), "l"(b));
}
__device__ __forceinline__ void cpa16(void* dst, const void* src) {
    unsigned s = (unsigned)__cvta_generic_to_shared(dst);
    asm volatile("cp.async.cg.shared.global [%0], [%1], 16;" :: "r"(s), "l"(src));
}

// Block: 512 threads (16 warps -> 4 per SMSP for latency hiding),
// tile 128 rows x 128 codes, K chunks of 32 floats, double-buffered
// cp.async. Thread (tx=tid%16, ty=(tid/16)%32) owns rows {ty+32i, i<4}
// and codes {tx+16j, j<8}. f32x2 packing over the d-dimension: one
// LDS.128 yields two aligned (d,d+1) pairs, zero packing MOVs. One f32x2
// accumulator per (row,code) (even/odd d halves), combined with a single
// fadd per score at code-tile end.
// Smem row pitch = 36 floats (144 B) for conflict-free 8-lane phases.
__global__ __launch_bounds__(512, 1) void k_argmin(const float4* __restrict__ cb4) {
    extern __shared__ float4 smem4[];
    char* sZ = (char*)smem4;                 // [2][128*144]
    char* sC = (char*)(smem4 + 2 * 1152);    // [2][128*144]
    const int tid = threadIdx.x;
    const int tx = tid & 15, ty = (tid >> 4) & 31;
    const int rowbase = blockIdx.x * 128;
    const int ld_d4 = tid & 7, ld_r = tid >> 3;   // ld_r in [0,64)

    float minv[4]; int mini[4]; float zn2r[4];
#pragma unroll
    for (int i = 0; i < 4; i++) {
        minv[i] = __int_as_float(0x7f800000);
        mini[i] = 0;
        zn2r[i] = g_zn2[rowbase + ty + 32 * i];
    }

    const float4* zt4 = g_zt4;
    // prologue: issue chunk (kt=0, ch=0) into buffer 0
    {
#pragma unroll
        for (int p = 0; p < 2; p++) {
            int r = ld_r + 64 * p;
            cpa16(sZ + r * 144 + ld_d4 * 16, &zt4[(size_t)(rowbase + r) * 64 + ld_d4]);
            cpa16(sC + r * 144 + ld_d4 * 16, &cb4[(size_t)r * 64 + ld_d4]);
        }
        asm volatile("cp.async.commit_group;" ::: "memory");
    }

    int buf = 0;
    for (int kt = 0; kt < 128; ++kt) {
        const int ktb = kt * 128;
        // prefetch ce for this code tile (consumed only at tile end)
        float ce_r[8];
#pragma unroll
        for (int j = 0; j < 8; j++) ce_r[j] = __ldg(&g_ce[ktb + tx + 16 * j]);

        ull acc[4][8];
#pragma unroll
        for (int i = 0; i < 4; i++)
#pragma unroll
            for (int j = 0; j < 8; j++) acc[i][j] = 0ull;

        for (int ch = 0; ch < 8; ++ch) {
            asm volatile("cp.async.wait_group 0;" ::: "memory");
            __syncthreads();
            // prefetch next chunk into the other buffer
            int nkt = kt, nch = ch + 1;
            if (nch == 8) { nch = 0; nkt = kt + 1; }
            if (nkt < 128) {
                char* dZ = sZ + (buf ^ 1) * 18432;
                char* dC = sC + (buf ^ 1) * 18432;
#pragma unroll
                for (int p = 0; p < 2; p++) {
                    int r = ld_r + 64 * p;
                    cpa16(dZ + r * 144 + ld_d4 * 16,
                          &zt4[(size_t)(rowbase + r) * 64 + nch * 8 + ld_d4]);
                    cpa16(dC + r * 144 + ld_d4 * 16,
                          &cb4[(size_t)(nkt * 128 + r) * 64 + nch * 8 + ld_d4]);
                }
                asm volatile("cp.async.commit_group;" ::: "memory");
            }
            // compute current buffer: 32 d-values
            const char* Zb = sZ + buf * 18432;
            const char* Cb = sC + buf * 18432;
#pragma unroll
            for (int d4 = 0; d4 < 8; ++d4) {
                ulonglong2 zv[4];
#pragma unroll
                for (int i = 0; i < 4; i++)
                    zv[i] = *(const ulonglong2*)(Zb + (ty + 32 * i) * 144 + d4 * 16);
#pragma unroll
                for (int j = 0; j < 8; j++) {
                    ulonglong2 cv =
                        *(const ulonglong2*)(Cb + (tx + 16 * j) * 144 + d4 * 16);
#pragma unroll
                    for (int i = 0; i < 4; i++) {
                        ffma2(acc[i][j], zv[i].x, cv.x);
                        ffma2(acc[i][j], zv[i].y, cv.y);
                    }
                }
            }
            buf ^= 1;
        }
        // epilogue: scores; d = fl( fl(zn2 + ce) - fl(2*g) )
#pragma unroll
        for (int i = 0; i < 4; i++) {
            float zn = zn2r[i];
#pragma unroll
            for (int j = 0; j < 8; j++) {
                float lo, hi; unpk2(acc[i][j], lo, hi);
                float g = __fadd_rn(lo, hi);
                int cidx = ktb + tx + 16 * j;
                float t = __fadd_rn(zn, ce_r[j]);
                float s = __fmaf_rn(-2.0f, g, t);
                // strict <: codes visited ascending -> lowest index wins ties
                if (s < minv[i]) { minv[i] = s; mini[i] = cidx; }
            }
        }
    }

    // cross-lane (tx) reduction, tie-break to lowest index
    __syncthreads();
    float* rv = (float*)smem4;
    int*   ri = (int*)(((char*)smem4) + 128 * 17 * 4);
#pragma unroll
    for (int i = 0; i < 4; i++) {
        int rl = ty + 32 * i;
        rv[rl * 17 + tx] = minv[i];
        ri[rl * 17 + tx] = mini[i];
    }
    __syncthreads();
    if (tid < 128) {
        float bv = rv[tid * 17]; int bi = ri[tid * 17];
#pragma unroll
        for (int t = 1; t < 16; t++) {
            float v = rv[tid * 17 + t]; int id = ri[tid * 17 + t];
            if (v < bv || (v == bv && id < bi)) { bv = v; bi = id; }
        }
        g_idx[rowbase + tid] = bi;
    }
}

// =====================================================================
// gather z_q = codebook[idx] and append idx (as float) if room
// =====================================================================
__global__ void k_gather(const float4* __restrict__ cb4, float* __restrict__ out,
                         int write_idx) {
    int t = blockIdx.x * 256 + threadIdx.x;
    int n = t >> 6, c4 = t & 63;
    int id = g_idx[n];
    ((float4*)out)[(size_t)n * 64 + c4] = cb4[(size_t)id * 64 + c4];
    if (write_idx && c4 == 0) out[NZQ + n] = (float)id;
}

// =====================================================================
extern "C" void kernel_launch(void* const* d_in, const int* in_sizes, int n_in,
                              void* d_out, int out_size) {
    const float* z  = (const float*)d_in[0];
    const float* cb = (const float*)d_in[1];

    void *ztp, *zn2p, *cep;
    cudaGetSymbolAddress(&ztp, g_zt4);
    cudaGetSymbolAddress(&zn2p, g_zn2);
    cudaGetSymbolAddress(&cep, g_ce);

    k_transpose<<<dim3(32, 8, 16), dim3(32, 8)>>>(z);
    k_rownorm<<<512, 256>>>((const float*)ztp, (float*)zn2p);
    k_rownorm<<<512, 256>>>(cb, (float*)cep);

    const int smem_bytes = 4608 * 16;  // 2 bufs x (Z+C) x 18432 B = 73728 B
    cudaFuncSetAttribute(k_argmin, cudaFuncAttributeMaxDynamicSharedMemorySize,
                         smem_bytes);
    k_argmin<<<128, 512, smem_bytes>>>((const float4*)cb);

    int write_idx = (out_size >= NZQ + NROWS) ? 1 : 0;
    k_gather<<<(NROWS * 64) / 256, 256>>>((const float4*)cb, (float*)d_out, write_idx);
}

// round 7
// speedup vs baseline: 2.8321x; 1.9273x over previous
#include <cuda_runtime.h>
#include <cuda_bf16.h>
#include <cstdint>

// VectorQuantizer: z[16,256,32,32] fp32, codebook[16384,256] fp32
// out: z_q [16,32,32,256] flattened (4,194,304 floats) then idx (16384) as float.

#define NROWS 16384
#define KCODES 16384
#define NZQ (16384*256)
#define KCAND 64
#define WINDOW 2.0e-4f

typedef unsigned int uint;

// ---- scratch (device globals; no allocation allowed) ----
__device__ float4        g_zt4[NROWS * 64];      // z transposed [N][256] fp32, 16 MB
__device__ float         g_zn2[NROWS];
__device__ float         g_ce[KCODES];
__device__ int           g_idx[NROWS];
__device__ __nv_bfloat16 g_zbf[NROWS * 256];     // 8 MB
__device__ __nv_bfloat16 g_cbbf[KCODES * 256];   // 8 MB
__device__ int           g_cand[NROWS * KCAND];  // 4 MB
__device__ int           g_ccnt[NROWS];

// =====================================================================
// helpers (baseline PTX only: works under compute_103 virtual arch)
// =====================================================================
__device__ __forceinline__ uint smem_u32(const void* p) {
    uint a;
    asm("{ .reg .u64 t; cvta.to.shared.u64 t, %1; cvt.u32.u64 %0, t; }"
        : "=r"(a) : "l"(p));
    return a;
}
__device__ __forceinline__ void cpa16(uint smem_dst, const void* src) {
    asm volatile("cp.async.cg.shared.global [%0], [%1], 16;"
                 :: "r"(smem_dst), "l"(src));
}
__device__ __forceinline__ void ldsm4(uint& r0, uint& r1, uint& r2, uint& r3,
                                      uint addr) {
    asm volatile("ldmatrix.sync.aligned.m8n8.x4.shared.b16 {%0,%1,%2,%3}, [%4];"
                 : "=r"(r0), "=r"(r1), "=r"(r2), "=r"(r3) : "r"(addr));
}
__device__ __forceinline__ void mma16816(float* c, const uint* a, const uint* b) {
    asm volatile("mma.sync.aligned.m16n8k16.row.col.f32.bf16.bf16.f32 "
                 "{%0,%1,%2,%3}, {%4,%5,%6,%7}, {%8,%9}, {%0,%1,%2,%3};"
                 : "+f"(c[0]), "+f"(c[1]), "+f"(c[2]), "+f"(c[3])
                 : "r"(a[0]), "r"(a[1]), "r"(a[2]), "r"(a[3]),
                   "r"(b[0]), "r"(b[1]));
}
// swizzled offset of 16B chunk ci (0..31) in a 512B row r (XOR on chunk idx)
__device__ __forceinline__ uint offsw(int r, int ci) {
    return (uint)r * 512u + (uint)((ci ^ (r & 7)) << 4);
}

// =====================================================================
// transpose z [B=16, C=256, HW=1024] -> zt [n = b*1024+hw][c]
// =====================================================================
__global__ void k_transpose(const float* __restrict__ z) {
    __shared__ float t[32][33];
    int b = blockIdx.z, c0 = blockIdx.y * 32, hw0 = blockIdx.x * 32;
    float* zt = (float*)g_zt4;
#pragma unroll
    for (int r = 0; r < 4; r++) {
        int c = c0 + threadIdx.y + 8 * r;
        t[threadIdx.y + 8 * r][threadIdx.x] =
            z[((size_t)(b * 256 + c)) * 1024 + hw0 + threadIdx.x];
    }
    __syncthreads();
#pragma unroll
    for (int r = 0; r < 4; r++) {
        int hw = hw0 + threadIdx.y + 8 * r;
        zt[((size_t)(b * 1024 + hw)) * 256 + c0 + threadIdx.x] =
            t[threadIdx.x][threadIdx.y + 8 * r];
    }
}

// =====================================================================
// row squared norms: rounded multiply + strictly sequential fp32 adds
// =====================================================================
__global__ void k_rownorm(const float* __restrict__ src, float* __restrict__ dst) {
    __shared__ float s[32 * 257];
    int base = blockIdx.x * 32;
    for (int off = threadIdx.x; off < 32 * 256; off += 256) {
        int r = off >> 8, d = off & 255;
        s[r * 257 + d] = src[(size_t)base * 256 + off];
    }
    __syncthreads();
    if (threadIdx.x < 32) {
        const float* row = &s[threadIdx.x * 257];
        float a = 0.f;
        for (int d = 0; d < 256; ++d) {
            float v = row[d];
            a = __fadd_rn(a, __fmul_rn(v, v));
        }
        dst[base + threadIdx.x] = a;
    }
}

// =====================================================================
// fp32 -> bf16 conversion (8 floats / thread) + counter zeroing
// =====================================================================
__device__ __forceinline__ uint packbf(float x, float y) {
    __nv_bfloat162 h = __floats2bfloat162_rn(x, y);
    return *reinterpret_cast<uint*>(&h);
}
__global__ void k_zbf16() {
    int t = blockIdx.x * 256 + threadIdx.x;   // 524288 threads
    float4 a = g_zt4[2 * t], b = g_zt4[2 * t + 1];
    uint4 o;
    o.x = packbf(a.x, a.y); o.y = packbf(a.z, a.w);
    o.z = packbf(b.x, b.y); o.w = packbf(b.z, b.w);
    ((uint4*)g_zbf)[t] = o;
}
__global__ void k_cbf16(const float4* __restrict__ cb) {
    int t = blockIdx.x * 256 + threadIdx.x;
    float4 a = cb[2 * t], b = cb[2 * t + 1];
    uint4 o;
    o.x = packbf(a.x, a.y); o.y = packbf(a.z, a.w);
    o.z = packbf(b.x, b.y); o.w = packbf(b.z, b.w);
    ((uint4*)g_cbbf)[t] = o;
}
__global__ void k_zerocnt() {
    g_ccnt[blockIdx.x * 256 + threadIdx.x] = 0;   // re-zeroed every replay
}

// =====================================================================
// main kernel: bf16 mma.sync GEMM + approx argmin + candidate collection
//
// grid 128 = 64 M-blocks x 2 N-halves. Block: 256 rows x (8192 codes as
// 128 tiles of 64). 8 warps: warpM=wid>>1 (4), warpN=wid&1 (2);
// warp tile 64 rows x 32 codes via m16n8k16 (4 mfrag x 4 nfrag).
// A tile (256x256 bf16 = 128 KB) resident; B double-buffered 2x32 KB.
// Smem rows 512 B with 16B-chunk XOR swizzle -> conflict-free ldmatrix.
// Scores are >0 (~256), so float-bits atomicMin on uint is order-safe.
// Tile 0 runs a min-only warm pass so the append window is seeded.
// =====================================================================
#define SM_A   0u
#define SM_B   131072u
#define SM_MIN 196608u
#define SMEM_BYTES 197632

__global__ __launch_bounds__(256, 1) void k_mma_argmin() {
    extern __shared__ char smem[];
    const uint sb = smem_u32(smem);
    uint* s_minu = (uint*)(smem + SM_MIN);
    const int tid = threadIdx.x, lane = tid & 31, wid = tid >> 5;
    const int warpM = wid >> 1, warpN = wid & 1;
    const int mblk = blockIdx.x >> 1, nhalf = blockIdx.x & 1;
    const int rowbase = mblk * 256, codebase0 = nhalf * 8192;

    // prologue: A (8192 chunks) + B tile 0 (2048 chunks)
    for (int c = tid; c < 8192; c += 256) {
        int r = c >> 5, ci = c & 31;
        cpa16(sb + SM_A + offsw(r, ci),
              (const char*)g_zbf + (size_t)(rowbase + r) * 512 + ci * 16);
    }
    for (int c = tid; c < 2048; c += 256) {
        int r = c >> 5, ci = c & 31;
        cpa16(sb + SM_B + offsw(r, ci),
              (const char*)g_cbbf + (size_t)(codebase0 + r) * 512 + ci * 16);
    }
    asm volatile("cp.async.commit_group;" ::: "memory");
    s_minu[tid] = 0x7f800000u;

    // ldmatrix address precompute
    const int rowA = (lane & 7) + ((lane >> 3) & 1) * 8;
    const int aK = lane >> 4;
    uint aAddr[4]; int aSw[4];
#pragma unroll
    for (int mf = 0; mf < 4; mf++) {
        int r = warpM * 64 + mf * 16 + rowA;
        aAddr[mf] = sb + SM_A + (uint)r * 512u;
        aSw[mf] = r & 7;
    }
    const int rowB = (lane & 7) + (lane >> 4) * 8;
    const int bK = (lane >> 3) & 1;
    const int nA = warpN * 32 + rowB, nB = nA + 16;
    const uint bOff0 = (uint)nA * 512u; const int bSw0 = nA & 7;
    const uint bOff1 = (uint)nB * 512u; const int bSw1 = nB & 7;

    float zn2r[8];
#pragma unroll
    for (int mf = 0; mf < 4; mf++)
#pragma unroll
        for (int h = 0; h < 2; h++)
            zn2r[mf * 2 + h] =
                g_zn2[rowbase + warpM * 64 + mf * 16 + (lane >> 2) + 8 * h];
    const int colq = warpN * 32 + (lane & 3) * 2;

    for (int kt = 0; kt < 128; ++kt) {
        const int buf = kt & 1;
        asm volatile("cp.async.wait_group 0;" ::: "memory");
        __syncthreads();
        if (kt + 1 < 128) {
            for (int c = tid; c < 2048; c += 256) {
                int r = c >> 5, ci = c & 31;
                cpa16(sb + SM_B + (uint)(buf ^ 1) * 32768u + offsw(r, ci),
                      (const char*)g_cbbf +
                          (size_t)(codebase0 + (kt + 1) * 64 + r) * 512 + ci * 16);
            }
            asm volatile("cp.async.commit_group;" ::: "memory");
        }
        const int ctile = codebase0 + kt * 64;
        float ce_r[8];
#pragma unroll
        for (int nf = 0; nf < 4; nf++)
#pragma unroll
            for (int q = 0; q < 2; q++)
                ce_r[nf * 2 + q] = __ldg(&g_ce[ctile + colq + nf * 8 + q]);

        float acc[4][4][4];
#pragma unroll
        for (int mf = 0; mf < 4; mf++)
#pragma unroll
            for (int nf = 0; nf < 4; nf++)
#pragma unroll
                for (int v = 0; v < 4; v++) acc[mf][nf][v] = 0.f;

        const uint bb = sb + SM_B + (uint)buf * 32768u;
#pragma unroll
        for (int ks = 0; ks < 16; ++ks) {
            uint b0[4], b1[4];
            ldsm4(b0[0], b0[1], b0[2], b0[3],
                  bb + bOff0 + (uint)(((2 * ks + bK) ^ bSw0) << 4));
            ldsm4(b1[0], b1[1], b1[2], b1[3],
                  bb + bOff1 + (uint)(((2 * ks + bK) ^ bSw1) << 4));
#pragma unroll
            for (int mf = 0; mf < 4; mf++) {
                uint a[4];
                ldsm4(a[0], a[1], a[2], a[3],
                      aAddr[mf] + (uint)(((2 * ks + aK) ^ aSw[mf]) << 4));
                mma16816(acc[mf][0], a, b0);
                mma16816(acc[mf][1], a, b0 + 2);
                mma16816(acc[mf][2], a, b1);
                mma16816(acc[mf][3], a, b1 + 2);
            }
        }

        // epilogue: tile 0 gets a min-only warm pass (pass 0) first
        for (int pass = (kt == 0 ? 0 : 1); pass < 2; ++pass) {
#pragma unroll
            for (int mf = 0; mf < 4; mf++)
#pragma unroll
                for (int h = 0; h < 2; h++) {
                    const int rl = warpM * 64 + mf * 16 + (lane >> 2) + 8 * h;
                    const float zn = zn2r[mf * 2 + h];
                    float m = __uint_as_float(s_minu[rl]);
#pragma unroll
                    for (int nf = 0; nf < 4; nf++)
#pragma unroll
                        for (int q = 0; q < 2; q++) {
                            float s = __fmaf_rn(-2.f, acc[mf][nf][h * 2 + q],
                                                __fadd_rn(zn, ce_r[nf * 2 + q]));
                            if (s < m + WINDOW) {
                                atomicMin(&s_minu[rl], __float_as_uint(s));
                                if (pass) {
                                    int pos = atomicAdd(&g_ccnt[rowbase + rl], 1);
                                    if (pos < KCAND)
                                        g_cand[(rowbase + rl) * KCAND + pos] =
                                            ctile + colq + nf * 8 + q;
                                }
                                if (s < m) m = s;
                            }
                        }
                }
            if (kt == 0 && pass == 0) __syncthreads();
        }
    }
}

// =====================================================================
// exact fp32 rescore of candidates (one warp per row)
// same summation form that has matched the reference bit-exactly:
// lo/hi fma over ascending d, g = fadd(lo,hi); s = fl(fl(zn+ce) - 2g)
// =====================================================================
__global__ void k_rescore(const float* __restrict__ cb) {
    const int gw = (blockIdx.x * blockDim.x + threadIdx.x) >> 5;
    const int lane = threadIdx.x & 31;
    if (gw >= NROWS) return;
    const float* zr = (const float*)g_zt4 + (size_t)gw * 256;
    const float zn = g_zn2[gw];
    const int cnt = g_ccnt[gw];
    float s = __int_as_float(0x7f800000);
    int bi = 0x7fffffff;
    if (cnt <= KCAND) {
        for (int ci = lane; ci < cnt; ci += 32) {
            int c = g_cand[gw * KCAND + ci];
            const float* er = cb + (size_t)c * 256;
            float lo = 0.f, hi = 0.f;
            for (int d = 0; d < 256; d += 2) {
                lo = __fmaf_rn(zr[d], er[d], lo);
                hi = __fmaf_rn(zr[d + 1], er[d + 1], hi);
            }
            float g = __fadd_rn(lo, hi);
            float sc = __fmaf_rn(-2.0f, g, __fadd_rn(zn, g_ce[c]));
            if (sc < s || (sc == s && c < bi)) { s = sc; bi = c; }
        }
    } else {
        // overflow fallback: exact full-row scan
        for (int c = lane; c < KCODES; c += 32) {
            const float* er = cb + (size_t)c * 256;
            float lo = 0.f, hi = 0.f;
            for (int d = 0; d < 256; d += 2) {
                lo = __fmaf_rn(zr[d], er[d], lo);
                hi = __fmaf_rn(zr[d + 1], er[d + 1], hi);
            }
            float g = __fadd_rn(lo, hi);
            float sc = __fmaf_rn(-2.0f, g, __fadd_rn(zn, g_ce[c]));
            if (sc < s || (sc == s && c < bi)) { s = sc; bi = c; }
        }
    }
#pragma unroll
    for (int o = 16; o; o >>= 1) {
        float s2 = __shfl_xor_sync(0xffffffffu, s, o);
        int b2 = __shfl_xor_sync(0xffffffffu, bi, o);
        if (s2 < s || (s2 == s && b2 < bi)) { s = s2; bi = b2; }
    }
    if (lane == 0) g_idx[gw] = bi;
}

// =====================================================================
// gather z_q = codebook[idx] and append idx (as float) if room
// =====================================================================
__global__ void k_gather(const float4* __restrict__ cb4, float* __restrict__ out,
                         int write_idx) {
    int t = blockIdx.x * 256 + threadIdx.x;
    int n = t >> 6, c4 = t & 63;
    int id = g_idx[n];
    ((float4*)out)[(size_t)n * 64 + c4] = cb4[(size_t)id * 64 + c4];
    if (write_idx && c4 == 0) out[NZQ + n] = (float)id;
}

// =====================================================================
extern "C" void kernel_launch(void* const* d_in, const int* in_sizes, int n_in,
                              void* d_out, int out_size) {
    const float* z  = (const float*)d_in[0];
    const float* cb = (const float*)d_in[1];

    void *ztp, *zn2p, *cep;
    cudaGetSymbolAddress(&ztp, g_zt4);
    cudaGetSymbolAddress(&zn2p, g_zn2);
    cudaGetSymbolAddress(&cep, g_ce);

    k_transpose<<<dim3(32, 8, 16), dim3(32, 8)>>>(z);
    k_rownorm<<<512, 256>>>((const float*)ztp, (float*)zn2p);
    k_rownorm<<<512, 256>>>(cb, (float*)cep);
    k_zbf16<<<2048, 256>>>();
    k_cbf16<<<2048, 256>>>((const float4*)cb);
    k_zerocnt<<<64, 256>>>();

    cudaFuncSetAttribute(k_mma_argmin, cudaFuncAttributeMaxDynamicSharedMemorySize,
                         SMEM_BYTES);
    k_mma_argmin<<<128, 256, SMEM_BYTES>>>();

    k_rescore<<<2048, 256>>>(cb);

    int write_idx = (out_size >= NZQ + NROWS) ? 1 : 0;
    k_gather<<<(NZQ / 4 + 255) / 256 * 1, 256>>>((const float4*)cb, (float*)d_out,
                                                 write_idx);
}

// round 8
// speedup vs baseline: 5.0152x; 1.7708x over previous
#include <cuda_runtime.h>
#include <cuda_bf16.h>
#include <cstdint>

// VectorQuantizer: z[16,256,32,32] fp32, codebook[16384,256] fp32
// out: z_q [16,32,32,256] flattened (4,194,304 floats) then idx (16384) as float.

#define NROWS 16384
#define KCODES 16384
#define NZQ (16384*256)
#define KCAND 64
#define WINDOW 2.0e-4f

typedef unsigned int uint;

// ---- scratch (device globals; no allocation allowed) ----
__device__ float4        g_zt4[NROWS * 64];      // z transposed [N][256] fp32, 16 MB
__device__ float         g_zn2[NROWS];
__device__ float         g_ce[KCODES];
__device__ int           g_idx[NROWS];
__device__ __nv_bfloat16 g_zbf[NROWS * 256];     // 8 MB
__device__ __nv_bfloat16 g_cbbf[KCODES * 256];   // 8 MB
__device__ int           g_cand[NROWS * KCAND];  // 4 MB
__device__ int           g_ccnt[NROWS];

// =====================================================================
// helpers (baseline PTX only: works under compute_103 virtual arch)
// =====================================================================
__device__ __forceinline__ uint smem_u32(const void* p) {
    uint a;
    asm("{ .reg .u64 t; cvta.to.shared.u64 t, %1; cvt.u32.u64 %0, t; }"
        : "=r"(a) : "l"(p));
    return a;
}
__device__ __forceinline__ void cpa16(uint smem_dst, const void* src) {
    asm volatile("cp.async.cg.shared.global [%0], [%1], 16;"
                 :: "r"(smem_dst), "l"(src));
}
__device__ __forceinline__ void ldsm4(uint& r0, uint& r1, uint& r2, uint& r3,
                                      uint addr) {
    asm volatile("ldmatrix.sync.aligned.m8n8.x4.shared.b16 {%0,%1,%2,%3}, [%4];"
                 : "=r"(r0), "=r"(r1), "=r"(r2), "=r"(r3) : "r"(addr));
}
__device__ __forceinline__ void mma16816(float* c, const uint* a, const uint* b) {
    asm volatile("mma.sync.aligned.m16n8k16.row.col.f32.bf16.bf16.f32 "
                 "{%0,%1,%2,%3}, {%4,%5,%6,%7}, {%8,%9}, {%0,%1,%2,%3};"
                 : "+f"(c[0]), "+f"(c[1]), "+f"(c[2]), "+f"(c[3])
                 : "r"(a[0]), "r"(a[1]), "r"(a[2]), "r"(a[3]),
                   "r"(b[0]), "r"(b[1]));
}
// swizzled offset of 16B chunk ci (0..31) in a 512B row r (XOR on chunk idx)
__device__ __forceinline__ uint offsw(int r, int ci) {
    return (uint)r * 512u + (uint)((ci ^ (r & 7)) << 4);
}

// =====================================================================
// launch #1: transpose z [B=16, C=256, HW=1024] -> zt [n = b*1024+hw][c]
// =====================================================================
__global__ void k_transpose(const float* __restrict__ z) {
    __shared__ float t[32][33];
    int b = blockIdx.z, c0 = blockIdx.y * 32, hw0 = blockIdx.x * 32;
    float* zt = (float*)g_zt4;
#pragma unroll
    for (int r = 0; r < 4; r++) {
        int c = c0 + threadIdx.y + 8 * r;
        t[threadIdx.y + 8 * r][threadIdx.x] =
            z[((size_t)(b * 256 + c)) * 1024 + hw0 + threadIdx.x];
    }
    __syncthreads();
#pragma unroll
    for (int r = 0; r < 4; r++) {
        int hw = hw0 + threadIdx.y + 8 * r;
        zt[((size_t)(b * 1024 + hw)) * 256 + c0 + threadIdx.x] =
            t[threadIdx.x][threadIdx.y + 8 * r];
    }
}

// =====================================================================
// launch #2: both row-norm sets in one kernel.
// rounded multiply + strictly sequential fp32 adds (XLA reduce semantics)
// blocks [0,512): z rows from g_zt4 -> g_zn2 ; [512,1024): codebook -> g_ce
// =====================================================================
__global__ void k_prep_norm(const float* __restrict__ cb) {
    __shared__ float s[32 * 257];
    const int zpart = blockIdx.x < 512;
    const int base = (zpart ? blockIdx.x : blockIdx.x - 512) * 32;
    const float* src = zpart ? (const float*)g_zt4 : cb;
    float* dst = zpart ? g_zn2 : g_ce;
    for (int off = threadIdx.x; off < 32 * 256; off += 256) {
        int r = off >> 8, d = off & 255;
        s[r * 257 + d] = src[(size_t)base * 256 + off];
    }
    __syncthreads();
    if (threadIdx.x < 32) {
        const float* row = &s[threadIdx.x * 257];
        float a = 0.f;
        for (int d = 0; d < 256; ++d) {
            float v = row[d];
            a = __fadd_rn(a, __fmul_rn(v, v));
        }
        dst[base + threadIdx.x] = a;
    }
}

// =====================================================================
// launch #3: fp32 -> bf16 (z and codebook) + zero candidate counters
// blocks [0,2048): z ; [2048,4096): codebook
// =====================================================================
__device__ __forceinline__ uint packbf(float x, float y) {
    __nv_bfloat162 h = __floats2bfloat162_rn(x, y);
    return *reinterpret_cast<uint*>(&h);
}
__global__ void k_prep_bf16(const float4* __restrict__ cb) {
    const int zpart = blockIdx.x < 2048;
    int t = (zpart ? blockIdx.x : blockIdx.x - 2048) * 256 + threadIdx.x;
    const float4* src = zpart ? g_zt4 : cb;
    float4 a = src[2 * t], b = src[2 * t + 1];
    uint4 o;
    o.x = packbf(a.x, a.y); o.y = packbf(a.z, a.w);
    o.z = packbf(b.x, b.y); o.w = packbf(b.z, b.w);
    ((uint4*)(zpart ? g_zbf : g_cbbf))[t] = o;
    if (!zpart && blockIdx.x < 2048 + 64)
        g_ccnt[(blockIdx.x - 2048) * 256 + threadIdx.x] = 0;  // re-zeroed per replay
}

// =====================================================================
// launch #4 (ncu capture slot): bf16 mma.sync GEMM + approx argmin +
// candidate collection.
//
// grid 128 = 64 M-blocks x 2 N-halves. Block: 512 threads, 16 warps.
// warpM = wid>>1 (8), warpN = wid&1 (2); warp tile 32 rows x 32 codes
// via m16n8k16 (2 mfrag x 4 nfrag, 32 acc regs -> no spill at 512 thr).
// A tile (256x256 bf16 = 128 KB) resident; B double-buffered 2x32 KB.
// Smem rows 512 B with 16B-chunk XOR swizzle -> conflict-free ldmatrix.
// Scores are >0 (~256), so float-bits atomicMin on uint is order-safe.
// Tile 0 runs a min-only warm pass so the append window is seeded.
// The true argmin always satisfies s* <= running min, so it is appended
// deterministically regardless of atomic timing.
// =====================================================================
#define SM_A   0u
#define SM_B   131072u
#define SM_MIN 196608u
#define SMEM_BYTES 197632

__global__ __launch_bounds__(512, 1) void k_mma_argmin() {
    extern __shared__ char smem[];
    const uint sb = smem_u32(smem);
    uint* s_minu = (uint*)(smem + SM_MIN);
    const int tid = threadIdx.x, lane = tid & 31, wid = tid >> 5;
    const int warpM = wid >> 1, warpN = wid & 1;
    const int mblk = blockIdx.x >> 1, nhalf = blockIdx.x & 1;
    const int rowbase = mblk * 256, codebase0 = nhalf * 8192;

    // prologue: A (8192 chunks) + B tile 0 (2048 chunks)
    for (int c = tid; c < 8192; c += 512) {
        int r = c >> 5, ci = c & 31;
        cpa16(sb + SM_A + offsw(r, ci),
              (const char*)g_zbf + (size_t)(rowbase + r) * 512 + ci * 16);
    }
    for (int c = tid; c < 2048; c += 512) {
        int r = c >> 5, ci = c & 31;
        cpa16(sb + SM_B + offsw(r, ci),
              (const char*)g_cbbf + (size_t)(codebase0 + r) * 512 + ci * 16);
    }
    asm volatile("cp.async.commit_group;" ::: "memory");
    if (tid < 256) s_minu[tid] = 0x7f800000u;

    // ldmatrix address precompute
    const int rowA = (lane & 7) + ((lane >> 3) & 1) * 8;
    const int aK = lane >> 4;
    uint aAddr[2]; int aSw[2];
#pragma unroll
    for (int mf = 0; mf < 2; mf++) {
        int r = warpM * 32 + mf * 16 + rowA;
        aAddr[mf] = sb + SM_A + (uint)r * 512u;
        aSw[mf] = r & 7;
    }
    const int rowB = (lane & 7) + (lane >> 4) * 8;
    const int bK = (lane >> 3) & 1;
    const int nA = warpN * 32 + rowB, nB = nA + 16;
    const uint bOff0 = (uint)nA * 512u; const int bSw0 = nA & 7;
    const uint bOff1 = (uint)nB * 512u; const int bSw1 = nB & 7;

    float zn2r[4];
#pragma unroll
    for (int mf = 0; mf < 2; mf++)
#pragma unroll
        for (int h = 0; h < 2; h++)
            zn2r[mf * 2 + h] =
                g_zn2[rowbase + warpM * 32 + mf * 16 + (lane >> 2) + 8 * h];
    const int colq = warpN * 32 + (lane & 3) * 2;

    for (int kt = 0; kt < 128; ++kt) {
        const int buf = kt & 1;
        asm volatile("cp.async.wait_group 0;" ::: "memory");
        __syncthreads();
        if (kt + 1 < 128) {
            for (int c = tid; c < 2048; c += 512) {
                int r = c >> 5, ci = c & 31;
                cpa16(sb + SM_B + (uint)(buf ^ 1) * 32768u + offsw(r, ci),
                      (const char*)g_cbbf +
                          (size_t)(codebase0 + (kt + 1) * 64 + r) * 512 + ci * 16);
            }
            asm volatile("cp.async.commit_group;" ::: "memory");
        }
        const int ctile = codebase0 + kt * 64;
        float ce_r[8];
#pragma unroll
        for (int nf = 0; nf < 4; nf++)
#pragma unroll
            for (int q = 0; q < 2; q++)
                ce_r[nf * 2 + q] = __ldg(&g_ce[ctile + colq + nf * 8 + q]);

        float acc[2][4][4];
#pragma unroll
        for (int mf = 0; mf < 2; mf++)
#pragma unroll
            for (int nf = 0; nf < 4; nf++)
#pragma unroll
                for (int v = 0; v < 4; v++) acc[mf][nf][v] = 0.f;

        const uint bb = sb + SM_B + (uint)buf * 32768u;
#pragma unroll
        for (int ks = 0; ks < 16; ++ks) {
            uint b0[4], b1[4];
            ldsm4(b0[0], b0[1], b0[2], b0[3],
                  bb + bOff0 + (uint)(((2 * ks + bK) ^ bSw0) << 4));
            ldsm4(b1[0], b1[1], b1[2], b1[3],
                  bb + bOff1 + (uint)(((2 * ks + bK) ^ bSw1) << 4));
#pragma unroll
            for (int mf = 0; mf < 2; mf++) {
                uint a[4];
                ldsm4(a[0], a[1], a[2], a[3],
                      aAddr[mf] + (uint)(((2 * ks + aK) ^ aSw[mf]) << 4));
                mma16816(acc[mf][0], a, b0);
                mma16816(acc[mf][1], a, b0 + 2);
                mma16816(acc[mf][2], a, b1);
                mma16816(acc[mf][3], a, b1 + 2);
            }
        }

        // epilogue: tile 0 gets a min-only warm pass (pass 0) first
        for (int pass = (kt == 0 ? 0 : 1); pass < 2; ++pass) {
#pragma unroll
            for (int mf = 0; mf < 2; mf++)
#pragma unroll
                for (int h = 0; h < 2; h++) {
                    const int rl = warpM * 32 + mf * 16 + (lane >> 2) + 8 * h;
                    const float zn = zn2r[mf * 2 + h];
                    float m = __uint_as_float(s_minu[rl]);
#pragma unroll
                    for (int nf = 0; nf < 4; nf++)
#pragma unroll
                        for (int q = 0; q < 2; q++) {
                            float s = __fmaf_rn(-2.f, acc[mf][nf][h * 2 + q],
                                                __fadd_rn(zn, ce_r[nf * 2 + q]));
                            if (s < m + WINDOW) {
                                atomicMin(&s_minu[rl], __float_as_uint(s));
                                if (pass) {
                                    int pos = atomicAdd(&g_ccnt[rowbase + rl], 1);
                                    if (pos < KCAND)
                                        g_cand[(rowbase + rl) * KCAND + pos] =
                                            ctile + colq + nf * 8 + q;
                                }
                                if (s < m) m = s;
                            }
                        }
                }
            if (kt == 0 && pass == 0) __syncthreads();
        }
    }
}

// =====================================================================
// launch #5: exact fp32 rescore of candidates (one warp per row)
// same summation form that has matched the reference bit-exactly:
// lo/hi fma over ascending d, g = fadd(lo,hi); s = fl(fl(zn+ce) - 2g)
// =====================================================================
__global__ void k_rescore(const float* __restrict__ cb) {
    const int gw = (blockIdx.x * blockDim.x + threadIdx.x) >> 5;
    const int lane = threadIdx.x & 31;
    if (gw >= NROWS) return;
    const float* zr = (const float*)g_zt4 + (size_t)gw * 256;
    const float zn = g_zn2[gw];
    const int cnt = g_ccnt[gw];
    float s = __int_as_float(0x7f800000);
    int bi = 0x7fffffff;
    if (cnt <= KCAND) {
        for (int ci = lane; ci < cnt; ci += 32) {
            int c = g_cand[gw * KCAND + ci];
            const float* er = cb + (size_t)c * 256;
            float lo = 0.f, hi = 0.f;
            for (int d = 0; d < 256; d += 2) {
                lo = __fmaf_rn(zr[d], er[d], lo);
                hi = __fmaf_rn(zr[d + 1], er[d + 1], hi);
            }
            float g = __fadd_rn(lo, hi);
            float sc = __fmaf_rn(-2.0f, g, __fadd_rn(zn, g_ce[c]));
            if (sc < s || (sc == s && c < bi)) { s = sc; bi = c; }
        }
    } else {
        // overflow fallback: exact full-row scan
        for (int c = lane; c < KCODES; c += 32) {
            const float* er = cb + (size_t)c * 256;
            float lo = 0.f, hi = 0.f;
            for (int d = 0; d < 256; d += 2) {
                lo = __fmaf_rn(zr[d], er[d], lo);
                hi = __fmaf_rn(zr[d + 1], er[d + 1], hi);
            }
            float g = __fadd_rn(lo, hi);
            float sc = __fmaf_rn(-2.0f, g, __fadd_rn(zn, g_ce[c]));
            if (sc < s || (sc == s && c < bi)) { s = sc; bi = c; }
        }
    }
#pragma unroll
    for (int o = 16; o; o >>= 1) {
        float s2 = __shfl_xor_sync(0xffffffffu, s, o);
        int b2 = __shfl_xor_sync(0xffffffffu, bi, o);
        if (s2 < s || (s2 == s && b2 < bi)) { s = s2; bi = b2; }
    }
    if (lane == 0) g_idx[gw] = bi;
}

// =====================================================================
// launch #6: gather z_q = codebook[idx] and append idx (as float) if room
// =====================================================================
__global__ void k_gather(const float4* __restrict__ cb4, float* __restrict__ out,
                         int write_idx) {
    int t = blockIdx.x * 256 + threadIdx.x;
    int n = t >> 6, c4 = t & 63;
    int id = g_idx[n];
    ((float4*)out)[(size_t)n * 64 + c4] = cb4[(size_t)id * 64 + c4];
    if (write_idx && c4 == 0) out[NZQ + n] = (float)id;
}

// =====================================================================
extern "C" void kernel_launch(void* const* d_in, const int* in_sizes, int n_in,
                              void* d_out, int out_size) {
    const float* z  = (const float*)d_in[0];
    const float* cb = (const float*)d_in[1];

    k_transpose<<<dim3(32, 8, 16), dim3(32, 8)>>>(z);
    k_prep_norm<<<1024, 256>>>(cb);
    k_prep_bf16<<<4096, 256>>>((const float4*)cb);

    cudaFuncSetAttribute(k_mma_argmin, cudaFuncAttributeMaxDynamicSharedMemorySize,
                         SMEM_BYTES);
    k_mma_argmin<<<128, 512, SMEM_BYTES>>>();

    k_rescore<<<2048, 256>>>(cb);

    int write_idx = (out_size >= NZQ + NROWS) ? 1 : 0;
    k_gather<<<4096, 256>>>((const float4*)cb, (float*)d_out, write_idx);
}

// round 9
// speedup vs baseline: 6.5849x; 1.3130x over previous
#include <cuda_runtime.h>
#include <cuda_bf16.h>
#include <cstdint>

// VectorQuantizer: z[16,256,32,32] fp32, codebook[16384,256] fp32
// out: z_q [16,32,32,256] flattened (4,194,304 floats) then idx (16384) as float.

#define NROWS 16384
#define KCODES 16384
#define NZQ (16384*256)
#define KCAND 64
#define WINDOW 2.0e-4f

typedef unsigned int uint;

// ---- scratch (device globals; no allocation allowed) ----
__device__ float4        g_zt4[NROWS * 64];      // z transposed [N][256] fp32, 16 MB
__device__ float         g_zn2[NROWS];
__device__ float         g_ce[KCODES];
__device__ int           g_idx[NROWS];
__device__ __nv_bfloat16 g_zbf[NROWS * 256];     // bf16, ldmatrix-swizzle baked, 8 MB
__device__ __nv_bfloat16 g_cbbf[KCODES * 256];   // bf16, ldmatrix-swizzle baked, 8 MB
__device__ int           g_cand[NROWS * KCAND];  // 4 MB
__device__ int           g_ccnt[NROWS];

// =====================================================================
// helpers (baseline sm_90 PTX only: compiles under compute_103 virtual)
// =====================================================================
__device__ __forceinline__ uint smem_u32(const void* p) {
    uint a;
    asm("{ .reg .u64 t; cvta.to.shared.u64 t, %1; cvt.u32.u64 %0, t; }"
        : "=r"(a) : "l"(p));
    return a;
}
__device__ __forceinline__ void mbar_init(uint addr, uint cnt) {
    asm volatile("mbarrier.init.shared.b64 [%0], %1;" :: "r"(addr), "r"(cnt) : "memory");
}
__device__ __forceinline__ void mbar_expect_tx(uint addr, uint tx) {
    asm volatile("mbarrier.arrive.expect_tx.shared.b64 _, [%0], %1;"
                 :: "r"(addr), "r"(tx) : "memory");
}
__device__ __forceinline__ void mbar_wait(uint addr, uint parity) {
    asm volatile("{\n\t.reg .pred P;\n\t"
                 "WL_%=:\n\t"
                 "mbarrier.try_wait.parity.acquire.cta.shared::cta.b64 P, [%0], %1, 0x989680;\n\t"
                 "@P bra WD_%=;\n\t"
                 "bra WL_%=;\n\t"
                 "WD_%=:\n\t}"
                 :: "r"(addr), "r"(parity) : "memory");
}
// 1D bulk copy gmem->smem, completion via mbarrier complete_tx
__device__ __forceinline__ void bulkcp(uint dst, const void* src, uint bytes,
                                       uint mbar) {
    asm volatile(
        "cp.async.bulk.shared::cluster.global.mbarrier::complete_tx::bytes "
        "[%0], [%1], %2, [%3];"
        :: "r"(dst), "l"(src), "r"(bytes), "r"(mbar) : "memory");
}
__device__ __forceinline__ void ldsm4(uint& r0, uint& r1, uint& r2, uint& r3,
                                      uint addr) {
    asm volatile("ldmatrix.sync.aligned.m8n8.x4.shared.b16 {%0,%1,%2,%3}, [%4];"
                 : "=r"(r0), "=r"(r1), "=r"(r2), "=r"(r3) : "r"(addr));
}
__device__ __forceinline__ void mma16816(float* c, const uint* a, const uint* b) {
    asm volatile("mma.sync.aligned.m16n8k16.row.col.f32.bf16.bf16.f32 "
                 "{%0,%1,%2,%3}, {%4,%5,%6,%7}, {%8,%9}, {%0,%1,%2,%3};"
                 : "+f"(c[0]), "+f"(c[1]), "+f"(c[2]), "+f"(c[3])
                 : "r"(a[0]), "r"(a[1]), "r"(a[2]), "r"(a[3]),
                   "r"(b[0]), "r"(b[1]));
}

// =====================================================================
// launch #1: transpose z [B=16, C=256, HW=1024] -> zt [n = b*1024+hw][c]
// =====================================================================
__global__ void k_transpose(const float* __restrict__ z) {
    __shared__ float t[32][33];
    int b = blockIdx.z, c0 = blockIdx.y * 32, hw0 = blockIdx.x * 32;
    float* zt = (float*)g_zt4;
#pragma unroll
    for (int r = 0; r < 4; r++) {
        int c = c0 + threadIdx.y + 8 * r;
        t[threadIdx.y + 8 * r][threadIdx.x] =
            z[((size_t)(b * 256 + c)) * 1024 + hw0 + threadIdx.x];
    }
    __syncthreads();
#pragma unroll
    for (int r = 0; r < 4; r++) {
        int hw = hw0 + threadIdx.y + 8 * r;
        zt[((size_t)(b * 1024 + hw)) * 256 + c0 + threadIdx.x] =
            t[threadIdx.x][threadIdx.y + 8 * r];
    }
}

// =====================================================================
// launch #2: both row-norm sets. rounded multiply + strictly sequential
// fp32 adds (XLA reduce semantics). blocks [0,512): z ; [512,1024): cb
// =====================================================================
__global__ void k_prep_norm(const float* __restrict__ cb) {
    __shared__ float s[32 * 257];
    const int zpart = blockIdx.x < 512;
    const int base = (zpart ? blockIdx.x : blockIdx.x - 512) * 32;
    const float* src = zpart ? (const float*)g_zt4 : cb;
    float* dst = zpart ? g_zn2 : g_ce;
    for (int off = threadIdx.x; off < 32 * 256; off += 256) {
        int r = off >> 8, d = off & 255;
        s[r * 257 + d] = src[(size_t)base * 256 + off];
    }
    __syncthreads();
    if (threadIdx.x < 32) {
        const float* row = &s[threadIdx.x * 257];
        float a = 0.f;
        for (int d = 0; d < 256; ++d) {
            float v = row[d];
            a = __fadd_rn(a, __fmul_rn(v, v));
        }
        dst[base + threadIdx.x] = a;
    }
}

// =====================================================================
// launch #3: fp32 -> bf16 with the ldmatrix XOR swizzle BAKED into gmem:
// 16B chunk ci of row c lands at byte  c*512 + ((ci ^ (c&7)) << 4).
// A 64-row-aligned block of this layout is bit-identical to the smem
// tile the MMA kernel wants, so one cp.async.bulk per tile suffices.
// blocks [0,2048): z ; [2048,4096): codebook (+ zero cand counters)
// =====================================================================
__device__ __forceinline__ uint packbf(float x, float y) {
    __nv_bfloat162 h = __floats2bfloat162_rn(x, y);
    return *reinterpret_cast<uint*>(&h);
}
__global__ void k_prep_bf16(const float4* __restrict__ cb) {
    const int zpart = blockIdx.x < 2048;
    int t = (zpart ? blockIdx.x : blockIdx.x - 2048) * 256 + threadIdx.x;
    const float4* src = zpart ? g_zt4 : cb;
    float4 a = src[2 * t], b = src[2 * t + 1];
    uint4 o;
    o.x = packbf(a.x, a.y); o.y = packbf(a.z, a.w);
    o.z = packbf(b.x, b.y); o.w = packbf(b.z, b.w);
    int c = t >> 5, ci = t & 31;
    size_t addr = (size_t)c * 512 + (uint)((ci ^ (c & 7)) << 4);
    *(uint4*)((char*)(zpart ? g_zbf : g_cbbf) + addr) = o;
    if (!zpart && blockIdx.x < 2048 + 64)
        g_ccnt[(blockIdx.x - 2048) * 256 + threadIdx.x] = 0;  // re-zeroed per replay
}

// =====================================================================
// launch #4: bf16 mma.sync GEMM + approx argmin + candidate collection.
//
// grid 128 = 64 M-blocks x 2 N-halves. 512 threads, 16 warps.
// warpM = wid>>1 (8), warpN = wid&1 (2); warp tile 32 rows x 32 codes.
// A (256x256 bf16 = 128 KB) resident via ONE cp.async.bulk; B tiles
// (64 codes x 256 d = 32 KB) double-buffered, ONE bulk copy per tile
// issued by thread 0 into an mbarrier -> zero LDGSTS issue cost.
// Swizzle is pre-baked in gmem so smem == previous hand-swizzled layout
// and all ldmatrix addressing is unchanged (conflict-free).
// Scores are >0 (~256) so float-bits atomicMin on uint is order-safe.
// Tile 0 runs a min-only warm pass; the true argmin always satisfies
// s* <= running min, so it is appended regardless of atomic timing.
// =====================================================================
#define SM_A   0u
#define SM_B   131072u
#define SM_MIN 196608u
#define SM_BAR 197632u
#define SMEM_BYTES 197664

__global__ __launch_bounds__(512, 1) void k_mma_argmin() {
    extern __shared__ char smem[];
    const uint sb = smem_u32(smem);
    uint* s_minu = (uint*)(smem + SM_MIN);
    const int tid = threadIdx.x, lane = tid & 31, wid = tid >> 5;
    const int warpM = wid >> 1, warpN = wid & 1;
    const int mblk = blockIdx.x >> 1, nhalf = blockIdx.x & 1;
    const int rowbase = mblk * 256, codebase0 = nhalf * 8192;

    const uint mbA = sb + SM_BAR, mbB = sb + SM_BAR + 8;  // mbB[2] at +8,+16

    if (tid == 0) {
        mbar_init(mbA, 1);
        mbar_init(mbB, 1);
        mbar_init(mbB + 8, 1);
    }
    if (tid < 256) s_minu[tid] = 0x7f800000u;
    __syncthreads();
    if (tid == 0) {
        mbar_expect_tx(mbA, 131072u);
        bulkcp(sb + SM_A, (const char*)g_zbf + (size_t)rowbase * 512, 131072u, mbA);
        mbar_expect_tx(mbB, 32768u);
        bulkcp(sb + SM_B, (const char*)g_cbbf + (size_t)codebase0 * 512, 32768u, mbB);
        mbar_expect_tx(mbB + 8, 32768u);
        bulkcp(sb + SM_B + 32768u,
               (const char*)g_cbbf + (size_t)(codebase0 + 64) * 512, 32768u, mbB + 8);
    }

    // ldmatrix address precompute (same swizzled layout as before)
    const int rowA = (lane & 7) + ((lane >> 3) & 1) * 8;
    const int aK = lane >> 4;
    uint aAddr[2]; int aSw[2];
#pragma unroll
    for (int mf = 0; mf < 2; mf++) {
        int r = warpM * 32 + mf * 16 + rowA;
        aAddr[mf] = sb + SM_A + (uint)r * 512u;
        aSw[mf] = r & 7;
    }
    const int rowB = (lane & 7) + (lane >> 4) * 8;
    const int bK = (lane >> 3) & 1;
    const int nA = warpN * 32 + rowB, nB = nA + 16;
    const uint bOff0 = (uint)nA * 512u; const int bSw0 = nA & 7;
    const uint bOff1 = (uint)nB * 512u; const int bSw1 = nB & 7;

    float zn2r[4];
#pragma unroll
    for (int mf = 0; mf < 2; mf++)
#pragma unroll
        for (int h = 0; h < 2; h++)
            zn2r[mf * 2 + h] =
                g_zn2[rowbase + warpM * 32 + mf * 16 + (lane >> 2) + 8 * h];
    const int colq = warpN * 32 + (lane & 3) * 2;

    mbar_wait(mbA, 0);   // A resident (also orders s_minu init via earlier sync)

    for (int kt = 0; kt < 128; ++kt) {
        const int buf = kt & 1;
        mbar_wait(mbB + 8u * buf, (kt >> 1) & 1);

        const int ctile = codebase0 + kt * 64;
        float ce_r[8];
#pragma unroll
        for (int nf = 0; nf < 4; nf++)
#pragma unroll
            for (int q = 0; q < 2; q++)
                ce_r[nf * 2 + q] = __ldg(&g_ce[ctile + colq + nf * 8 + q]);

        float acc[2][4][4];
#pragma unroll
        for (int mf = 0; mf < 2; mf++)
#pragma unroll
            for (int nf = 0; nf < 4; nf++)
#pragma unroll
                for (int v = 0; v < 4; v++) acc[mf][nf][v] = 0.f;

        const uint bb = sb + SM_B + (uint)buf * 32768u;
#pragma unroll
        for (int ks = 0; ks < 16; ++ks) {
            uint b0[4], b1[4];
            ldsm4(b0[0], b0[1], b0[2], b0[3],
                  bb + bOff0 + (uint)(((2 * ks + bK) ^ bSw0) << 4));
            ldsm4(b1[0], b1[1], b1[2], b1[3],
                  bb + bOff1 + (uint)(((2 * ks + bK) ^ bSw1) << 4));
#pragma unroll
            for (int mf = 0; mf < 2; mf++) {
                uint a[4];
                ldsm4(a[0], a[1], a[2], a[3],
                      aAddr[mf] + (uint)(((2 * ks + aK) ^ aSw[mf]) << 4));
                mma16816(acc[mf][0], a, b0);
                mma16816(acc[mf][1], a, b0 + 2);
                mma16816(acc[mf][2], a, b1);
                mma16816(acc[mf][3], a, b1 + 2);
            }
        }

        // epilogue: tile 0 gets a min-only warm pass (pass 0) first
        for (int pass = (kt == 0 ? 0 : 1); pass < 2; ++pass) {
#pragma unroll
            for (int mf = 0; mf < 2; mf++)
#pragma unroll
                for (int h = 0; h < 2; h++) {
                    const int rl = warpM * 32 + mf * 16 + (lane >> 2) + 8 * h;
                    const float zn = zn2r[mf * 2 + h];
                    float m = __uint_as_float(s_minu[rl]);
#pragma unroll
                    for (int nf = 0; nf < 4; nf++)
#pragma unroll
                        for (int q = 0; q < 2; q++) {
                            float s = __fmaf_rn(-2.f, acc[mf][nf][h * 2 + q],
                                                __fadd_rn(zn, ce_r[nf * 2 + q]));
                            if (s < m + WINDOW) {
                                atomicMin(&s_minu[rl], __float_as_uint(s));
                                if (pass) {
                                    int pos = atomicAdd(&g_ccnt[rowbase + rl], 1);
                                    if (pos < KCAND)
                                        g_cand[(rowbase + rl) * KCAND + pos] =
                                            ctile + colq + nf * 8 + q;
                                }
                                if (s < m) m = s;
                            }
                        }
                }
            if (kt == 0 && pass == 0) __syncthreads();
        }

        __syncthreads();   // all warps done reading buf before refill
        if (tid == 0 && kt + 2 < 128) {
            mbar_expect_tx(mbB + 8u * buf, 32768u);
            bulkcp(sb + SM_B + (uint)buf * 32768u,
                   (const char*)g_cbbf + (size_t)(codebase0 + (kt + 2) * 64) * 512,
                   32768u, mbB + 8u * buf);
        }
    }
}

// =====================================================================
// launch #5: exact fp32 rescore of candidates (one warp per row).
// Identical arithmetic order as always (lo/hi fma ascending d,
// g = fadd(lo,hi), s = fl(fl(zn+ce) - 2g)); float4 loads only change
// the load width, not rounding.
// =====================================================================
__global__ void k_rescore(const float* __restrict__ cb) {
    const int gw = (blockIdx.x * blockDim.x + threadIdx.x) >> 5;
    const int lane = threadIdx.x & 31;
    if (gw >= NROWS) return;
    const float4* zr4 = (const float4*)((const float*)g_zt4 + (size_t)gw * 256);
    const float zn = g_zn2[gw];
    const int cnt = g_ccnt[gw];
    float s = __int_as_float(0x7f800000);
    int bi = 0x7fffffff;
    if (cnt <= KCAND) {
        for (int ci = lane; ci < cnt; ci += 32) {
            int c = g_cand[gw * KCAND + ci];
            const float4* er4 = (const float4*)(cb + (size_t)c * 256);
            float lo = 0.f, hi = 0.f;
#pragma unroll 8
            for (int d4 = 0; d4 < 64; ++d4) {
                float4 zv = zr4[d4];
                float4 ev = __ldg(&er4[d4]);
                lo = __fmaf_rn(zv.x, ev.x, lo);
                hi = __fmaf_rn(zv.y, ev.y, hi);
                lo = __fmaf_rn(zv.z, ev.z, lo);
                hi = __fmaf_rn(zv.w, ev.w, hi);
            }
            float g = __fadd_rn(lo, hi);
            float sc = __fmaf_rn(-2.0f, g, __fadd_rn(zn, g_ce[c]));
            if (sc < s || (sc == s && c < bi)) { s = sc; bi = c; }
        }
    } else {
        // overflow fallback: exact full-row scan
        for (int c = lane; c < KCODES; c += 32) {
            const float4* er4 = (const float4*)(cb + (size_t)c * 256);
            float lo = 0.f, hi = 0.f;
            for (int d4 = 0; d4 < 64; ++d4) {
                float4 zv = zr4[d4];
                float4 ev = __ldg(&er4[d4]);
                lo = __fmaf_rn(zv.x, ev.x, lo);
                hi = __fmaf_rn(zv.y, ev.y, hi);
                lo = __fmaf_rn(zv.z, ev.z, lo);
                hi = __fmaf_rn(zv.w, ev.w, hi);
            }
            float g = __fadd_rn(lo, hi);
            float sc = __fmaf_rn(-2.0f, g, __fadd_rn(zn, g_ce[c]));
            if (sc < s || (sc == s && c < bi)) { s = sc; bi = c; }
        }
    }
#pragma unroll
    for (int o = 16; o; o >>= 1) {
        float s2 = __shfl_xor_sync(0xffffffffu, s, o);
        int b2 = __shfl_xor_sync(0xffffffffu, bi, o);
        if (s2 < s || (s2 == s && b2 < bi)) { s = s2; bi = b2; }
    }
    if (lane == 0) g_idx[gw] = bi;
}

// =====================================================================
// launch #6: gather z_q = codebook[idx] and append idx (as float) if room
// =====================================================================
__global__ void k_gather(const float4* __restrict__ cb4, float* __restrict__ out,
                         int write_idx) {
    int t = blockIdx.x * 256 + threadIdx.x;
    int n = t >> 6, c4 = t & 63;
    int id = g_idx[n];
    ((float4*)out)[(size_t)n * 64 + c4] = cb4[(size_t)id * 64 + c4];
    if (write_idx && c4 == 0) out[NZQ + n] = (float)id;
}

// =====================================================================
extern "C" void kernel_launch(void* const* d_in, const int* in_sizes, int n_in,
                              void* d_out, int out_size) {
    const float* z  = (const float*)d_in[0];
    const float* cb = (const float*)d_in[1];

    k_transpose<<<dim3(32, 8, 16), dim3(32, 8)>>>(z);
    k_prep_norm<<<1024, 256>>>(cb);
    k_prep_bf16<<<4096, 256>>>((const float4*)cb);

    cudaFuncSetAttribute(k_mma_argmin, cudaFuncAttributeMaxDynamicSharedMemorySize,
                         SMEM_BYTES);
    k_mma_argmin<<<128, 512, SMEM_BYTES>>>();

    k_rescore<<<2048, 256>>>(cb);

    int write_idx = (out_size >= NZQ + NROWS) ? 1 : 0;
    k_gather<<<4096, 256>>>((const float4*)cb, (float*)d_out, write_idx);
}